// round 14
// baseline (speedup 1.0000x reference)
#include <cuda_runtime.h>
#include <cuda_fp16.h>
#include <math.h>
#include <stdint.h>

// Problem constants
constexpr int NB = 8;
constexpr int L  = 4096;
constexpr int S  = 4096;
constexpr int E  = 256;
constexpr int H  = 8;
constexpr int D  = 32;
constexpr int NL = NB * L;   // 32768
constexpr int NS = NB * S;   // 32768
constexpr float EPS = 1e-6f;
constexpr int KV_SPLIT = 8;

// ---------------- scratch (device globals; no allocation allowed) ----------------
__device__ __half g_Qf[(size_t)NL * E];      // masked elu(Q)+1, fp16
__device__ __half g_Kf[(size_t)NS * E];      // masked elu(K)+1, fp16
__device__ __half g_Vm[(size_t)NS * E];      // masked V/S, fp16
__device__ __half g_Oh[(size_t)NL * E];      // attn output, fp16
__device__ __half g_qh[(size_t)NL * E];      // fp16 copies of inputs
__device__ __half g_kh[(size_t)NS * E];
__device__ __half g_vh[(size_t)NS * E];
__device__ __half g_Wh[4][(size_t)E * E];    // Wq, Wk, Wv, Wm in fp16
__device__ float  g_KV[(size_t)NB * H * D * D];
__device__ float  g_Ksum[(size_t)NB * H * D];
__device__ float  g_KVp[KV_SPLIT][(size_t)NB * H * D * D];
__device__ float  g_Ksump[KV_SPLIT][(size_t)NB * H * D];
__device__ float  g_qm[NL];
__device__ float  g_km[NS];
__device__ int    g_mask_mode;

// ---------------- helpers ----------------
__device__ __forceinline__ uint32_t smem_u32(const void* p) {
    uint32_t r;
    asm("{ .reg .u64 t; cvta.to.shared.u64 t, %1; cvt.u32.u64 %0, t; }" : "=r"(r) : "l"(p));
    return r;
}

__device__ __forceinline__ uint32_t pack_h2(float x, float y) {
    __half2 h = __floats2half2_rn(x, y);
    return *(uint32_t*)&h;
}

__device__ __forceinline__ void ldmx4(uint32_t (&r)[4], uint32_t addr) {
    asm volatile("ldmatrix.sync.aligned.m8n8.x4.shared.b16 {%0,%1,%2,%3}, [%4];"
                 : "=r"(r[0]), "=r"(r[1]), "=r"(r[2]), "=r"(r[3]) : "r"(addr));
}

__device__ __forceinline__ void mma_f16(float (&d)[4], const uint32_t (&a)[4],
                                        uint32_t b0, uint32_t b1) {
    asm volatile(
        "mma.sync.aligned.m16n8k16.row.col.f32.f16.f16.f32 "
        "{%0,%1,%2,%3}, {%4,%5,%6,%7}, {%8,%9}, {%0,%1,%2,%3};"
        : "+f"(d[0]), "+f"(d[1]), "+f"(d[2]), "+f"(d[3])
        : "r"(a[0]), "r"(a[1]), "r"(a[2]), "r"(a[3]), "r"(b0), "r"(b1));
}

__device__ __forceinline__ void cp_async16(uint32_t dst, const void* src) {
    asm volatile("cp.async.cg.shared.global [%0], [%1], 16;" :: "r"(dst), "l"(src) : "memory");
}
__device__ __forceinline__ void cp_commit() {
    asm volatile("cp.async.commit_group;" ::: "memory");
}
__device__ __forceinline__ void cp_wait2() {
    asm volatile("cp.async.wait_group 2;" ::: "memory");
}

// ---------------- mask dtype detection + conversion ----------------
__global__ void detect_mask_kernel(const void* mask) {
    __shared__ int s_off1, s_3f;
    const int tid = threadIdx.x;
    if (tid == 0) { s_off1 = 0; s_3f = 0; }
    __syncthreads();
    unsigned char c = ((const unsigned char*)mask)[tid];
    if ((tid & 3) == 1 && c == 1) atomicOr(&s_off1, 1);
    if (c == 0x3F)                atomicOr(&s_3f, 1);
    __syncthreads();
    if (tid == 0) g_mask_mode = s_off1 ? 0 : (s_3f ? 2 : 1);
}

__global__ void convert_mask_kernel(const void* __restrict__ m, float* __restrict__ out, int n) {
    int i = blockIdx.x * blockDim.x + threadIdx.x;
    if (i >= n) return;
    int mode = g_mask_mode;
    float v;
    if (mode == 0)      v = ((const unsigned char*)m)[i] ? 1.f : 0.f;
    else if (mode == 1) v = ((const int*)m)[i]           ? 1.f : 0.f;
    else                v = (((const float*)m)[i] != 0.f) ? 1.f : 0.f;
    out[i] = v;
}

// ---------------- fp32 -> fp16 conversion (inputs + weights) ----------------
__global__ void cvt_inputs_kernel(const float* __restrict__ a, const float* __restrict__ b,
                                  const float* __restrict__ c,
                                  __half* __restrict__ da, __half* __restrict__ db,
                                  __half* __restrict__ dc) {
    const int seg = blockIdx.y;
    const float* s = (seg == 0) ? a : (seg == 1) ? b : c;
    __half*      d = (seg == 0) ? da : (seg == 1) ? db : dc;
    size_t i = ((size_t)blockIdx.x * blockDim.x + threadIdx.x) * 8;
    float4 f0 = *(const float4*)&s[i];
    float4 f1 = *(const float4*)&s[i + 4];
    uint4 o = make_uint4(pack_h2(f0.x, f0.y), pack_h2(f0.z, f0.w),
                         pack_h2(f1.x, f1.y), pack_h2(f1.z, f1.w));
    *(uint4*)&d[i] = o;
}

__global__ void cvt_weights_kernel(const float* __restrict__ w0, const float* __restrict__ w1,
                                   const float* __restrict__ w2, const float* __restrict__ w3) {
    const int seg = blockIdx.y;
    const float* s = (seg == 0) ? w0 : (seg == 1) ? w1 : (seg == 2) ? w2 : w3;
    __half*      d = g_Wh[seg];
    size_t i = ((size_t)blockIdx.x * blockDim.x + threadIdx.x) * 8;
    float4 f0 = *(const float4*)&s[i];
    float4 f1 = *(const float4*)&s[i + 4];
    uint4 o = make_uint4(pack_h2(f0.x, f0.y), pack_h2(f0.z, f0.w),
                         pack_h2(f1.x, f1.y), pack_h2(f1.z, f1.w));
    *(uint4*)&d[i] = o;
}

// ---------------- fp16 tensor-core GEMM: C = A @ W^T (+bias) with epilogue ----------------
// A: [M, E] row-major fp16, W: [E, E] row-major fp16 (C[m,n] = sum_k A[m,k]*W[n,k])
// mode 0: plain    mode 1: (elu(x)+1) * rowmask    mode 2: x * rowmask * scale
// outhalf: 0 -> C is float*, 1 -> C is __half*
#define BM 128
#define BN 128
#define BK 32
#define BUFB 8192
#define NSTAGE 4
constexpr int GEMM_DSMEM = 2 * NSTAGE * BUFB;   // 64KB

__global__ __launch_bounds__(256, 2)
void gemm_f16(const __half* __restrict__ A,
              const __half* __restrict__ W,
              const float* __restrict__ bias,
              void* __restrict__ Cv,
              const float* __restrict__ rowmask,
              float scale, int mode, int outhalf)
{
    extern __shared__ __align__(16) unsigned char dynsm[];
    const uint32_t sA = smem_u32(dynsm);
    const uint32_t sB = sA + NSTAGE * BUFB;

    const int tid  = threadIdx.x;
    const int wid  = tid >> 5;
    const int lane = tid & 31;
    const int m0   = blockIdx.y * BM;
    const int n0   = blockIdx.x * BN;
    const int wm   = (wid & 1) * 64;
    const int wn   = (wid >> 1) * 32;
    const int g    = lane >> 2;
    const int tg   = lane & 3;

    // ---- fill indices ----
    int fr[2], fc[2];
    uint32_t foff[2];
#pragma unroll
    for (int p = 0; p < 2; p++) {
        int idx = p * 256 + tid;
        fr[p] = idx >> 2;
        fc[p] = idx & 3;
        foff[p] = (uint32_t)(fr[p] * 64 + ((fc[p] ^ ((fr[p] >> 1) & 3)) << 4));
    }

    // ---- ldmatrix addresses ----
    uint32_t adA[4][2], adB[2][2];
#pragma unroll
    for (int i = 0; i < 4; i++) {
        int r = wm + i * 16 + ((lane >> 3) & 1) * 8 + (lane & 7);
#pragma unroll
        for (int s = 0; s < 2; s++) {
            int kc = 2 * s + (lane >> 4);
            adA[i][s] = sA + (uint32_t)(r * 64 + ((kc ^ ((r >> 1) & 3)) << 4));
        }
    }
#pragma unroll
    for (int jp = 0; jp < 2; jp++) {
        int r = wn + (2 * jp + ((lane >> 3) >> 1)) * 8 + (lane & 7);
#pragma unroll
        for (int s = 0; s < 2; s++) {
            int kc = 2 * s + ((lane >> 3) & 1);
            adB[jp][s] = sB + (uint32_t)(r * 64 + ((kc ^ ((r >> 1) & 3)) << 4));
        }
    }

    float acc[4][4][4];
#pragma unroll
    for (int i = 0; i < 4; i++)
#pragma unroll
        for (int j = 0; j < 4; j++)
#pragma unroll
            for (int r = 0; r < 4; r++) acc[i][j][r] = 0.f;

    auto issue_stage = [&](int s) {
        const uint32_t so = (uint32_t)(s & 3) * BUFB;
#pragma unroll
        for (int p = 0; p < 2; p++) {
            const __half* srcA = A + (size_t)(m0 + fr[p]) * E + s * BK + fc[p] * 8;
            cp_async16(sA + so + foff[p], srcA);
            const __half* srcB = W + (size_t)(n0 + fr[p]) * E + s * BK + fc[p] * 8;
            cp_async16(sB + so + foff[p], srcB);
        }
    };

    issue_stage(0); cp_commit();
    issue_stage(1); cp_commit();
    issue_stage(2); cp_commit();

    constexpr int NITER = E / BK;   // 8
#pragma unroll
    for (int c = 0; c < NITER; c++) {
        cp_wait2();
        __syncthreads();
        if (c + 3 < NITER) issue_stage(c + 3);
        cp_commit();

        const uint32_t boff = (uint32_t)(c & 3) * BUFB;
#pragma unroll
        for (int s = 0; s < 2; s++) {
            uint32_t a[4][4];
#pragma unroll
            for (int i = 0; i < 4; i++) ldmx4(a[i], adA[i][s] + boff);
            uint32_t bb[2][4];
#pragma unroll
            for (int jp = 0; jp < 2; jp++) ldmx4(bb[jp], adB[jp][s] + boff);
#pragma unroll
            for (int i = 0; i < 4; i++) {
#pragma unroll
                for (int j = 0; j < 4; j++) {
                    const int jp = j >> 1, hi = j & 1;
                    mma_f16(acc[i][j], a[i], bb[jp][hi * 2], bb[jp][hi * 2 + 1]);
                }
            }
        }
    }

    // ---- epilogue ----
    float*  Cf = (float*)Cv;
    __half* Ch = (__half*)Cv;
#pragma unroll
    for (int i = 0; i < 4; i++) {
        const int r0 = m0 + wm + i * 16 + g;
        const int r1 = r0 + 8;
        float rm0 = 0.f, rm1 = 0.f;
        if (mode != 0) { rm0 = rowmask[r0]; rm1 = rowmask[r1]; }
#pragma unroll
        for (int j = 0; j < 4; j++) {
            const int col = n0 + wn + j * 8 + 2 * tg;
            float b0 = 0.f, b1 = 0.f;
            if (bias) { b0 = bias[col]; b1 = bias[col + 1]; }
            float v0 = acc[i][j][0] + b0;
            float v1 = acc[i][j][1] + b1;
            float v2 = acc[i][j][2] + b0;
            float v3 = acc[i][j][3] + b1;
            if (mode == 1) {
                v0 = ((v0 > 0.f) ? (v0 + 1.f) : expf(v0)) * rm0;
                v1 = ((v1 > 0.f) ? (v1 + 1.f) : expf(v1)) * rm0;
                v2 = ((v2 > 0.f) ? (v2 + 1.f) : expf(v2)) * rm1;
                v3 = ((v3 > 0.f) ? (v3 + 1.f) : expf(v3)) * rm1;
            } else if (mode == 2) {
                v0 *= rm0 * scale; v1 *= rm0 * scale;
                v2 *= rm1 * scale; v3 *= rm1 * scale;
            }
            if (outhalf) {
                *(uint32_t*)&Ch[(size_t)r0 * E + col] = pack_h2(v0, v1);
                *(uint32_t*)&Ch[(size_t)r1 * E + col] = pack_h2(v2, v3);
            } else {
                *(float2*)&Cf[(size_t)r0 * E + col] = make_float2(v0, v1);
                *(float2*)&Cf[(size_t)r1 * E + col] = make_float2(v2, v3);
            }
        }
    }
}

// ---------------- KV aggregation (s-split, fp16 in): partial KV[n,h,d,v], Ksum ----------------
__global__ __launch_bounds__(256)
void kv_agg_kernel(const __half* __restrict__ Kf, const __half* __restrict__ Vm)
{
    const int n = blockIdx.x >> 3;
    const int h = blockIdx.x & 7;
    const int split = blockIdx.y;
    const int sbeg = split * (S / KV_SPLIT);
    const int send = sbeg + (S / KV_SPLIT);

    __shared__ float sK[64][40];
    __shared__ float sV[64][40];
    __shared__ float red[4][64][16];

    const int tid = threadIdx.x;
    const int g = tid >> 6;
    const int t = tid & 63;
    const int db = (t >> 3) << 2;
    const int vb = (t & 7) << 2;

    // fp16 loader: each thread loads 8 halves (16B) per matrix per tile
    const int lr = tid >> 2;            // row 0..63
    const int lc = (tid & 3) << 3;      // col 0,8,16,24

    float acc[4][4];
#pragma unroll
    for (int i = 0; i < 4; i++)
#pragma unroll
        for (int j = 0; j < 4; j++) acc[i][j] = 0.f;
    float ksum = 0.f;

    const size_t base = (size_t)n * S * E + (size_t)h * D;

    for (int s0 = sbeg; s0 < send; s0 += 64) {
        {
            size_t off = base + (size_t)(s0 + lr) * E + lc;
            uint4 kr = *(const uint4*)&Kf[off];
            uint4 vr = *(const uint4*)&Vm[off];
            const __half2* kh = (const __half2*)&kr;
            const __half2* vh = (const __half2*)&vr;
#pragma unroll
            for (int e = 0; e < 4; e++) {
                float2 kf = __half22float2(kh[e]);
                float2 vf = __half22float2(vh[e]);
                sK[lr][lc + 2 * e]     = kf.x;
                sK[lr][lc + 2 * e + 1] = kf.y;
                sV[lr][lc + 2 * e]     = vf.x;
                sV[lr][lc + 2 * e + 1] = vf.y;
            }
        }
        __syncthreads();

        for (int ss = g; ss < 64; ss += 4) {
            float4 k4 = *(const float4*)&sK[ss][db];
            float4 v4 = *(const float4*)&sV[ss][vb];
            acc[0][0] += k4.x * v4.x; acc[0][1] += k4.x * v4.y; acc[0][2] += k4.x * v4.z; acc[0][3] += k4.x * v4.w;
            acc[1][0] += k4.y * v4.x; acc[1][1] += k4.y * v4.y; acc[1][2] += k4.y * v4.z; acc[1][3] += k4.y * v4.w;
            acc[2][0] += k4.z * v4.x; acc[2][1] += k4.z * v4.y; acc[2][2] += k4.z * v4.z; acc[2][3] += k4.z * v4.w;
            acc[3][0] += k4.w * v4.x; acc[3][1] += k4.w * v4.y; acc[3][2] += k4.w * v4.z; acc[3][3] += k4.w * v4.w;
        }
        if (g == 0 && t < 32) {
#pragma unroll
            for (int ss = 0; ss < 64; ss++) ksum += sK[ss][t];
        }
        __syncthreads();
    }

#pragma unroll
    for (int jd = 0; jd < 4; jd++)
#pragma unroll
        for (int jv = 0; jv < 4; jv++) red[g][t][jd * 4 + jv] = acc[jd][jv];
    __syncthreads();

    const size_t kvbase = (size_t)((n * H + h) * D) * D;
#pragma unroll
    for (int q = 0; q < 4; q++) {
        int o = tid * 4 + q;
        int d = o >> 5, v = o & 31;
        int tt = ((d >> 2) << 3) | (v >> 2);
        int jj = ((d & 3) << 2) | (v & 3);
        float val = red[0][tt][jj] + red[1][tt][jj] + red[2][tt][jj] + red[3][tt][jj];
        g_KVp[split][kvbase + (size_t)d * D + v] = val;
    }
    if (g == 0 && t < 32) g_Ksump[split][(size_t)(n * H + h) * D + t] = ksum;
}

// ---------------- KV partial reduction ----------------
__global__ void kv_reduce_kernel() {
    const int NKV = NB * H * D * D;
    const int NKS = NB * H * D;
    int i = blockIdx.x * blockDim.x + threadIdx.x;
    if (i < NKV) {
        float s = 0.f;
#pragma unroll
        for (int p = 0; p < KV_SPLIT; p++) s += g_KVp[p][i];
        g_KV[i] = s;
    } else if (i < NKV + NKS) {
        int j = i - NKV;
        float s = 0.f;
#pragma unroll
        for (int p = 0; p < KV_SPLIT; p++) s += g_Ksump[p][j];
        g_Ksum[j] = s;
    }
}

// ---------------- attention apply: Oh = fp16( (Qf @ KV) * Z * S ) ----------------
__global__ __launch_bounds__(256)
void attn_kernel(const __half* __restrict__ Qf, __half* __restrict__ O)
{
    const int bid  = blockIdx.x;
    const int n    = bid >> 12;
    const int h    = (bid >> 9) & 7;
    const int lgrp = bid & 511;

    __shared__ float sKV[32][32];
    __shared__ float sKs[32];

    const int tid = threadIdx.x;
    const float* kvp = g_KV + (size_t)((n * H + h) * D) * D;
    ((float4*)sKV)[tid] = ((const float4*)kvp)[tid];
    if (tid < 32) sKs[tid] = g_Ksum[(size_t)(n * H + h) * D + tid];
    __syncthreads();

    const int w = tid >> 5, lane = tid & 31;
    const int l = (lgrp << 3) | w;
    const size_t ro = ((size_t)n * L + l) * E + (size_t)h * D;

    float qf = __half2float(Qf[ro + lane]);
    float z = qf * sKs[lane];
#pragma unroll
    for (int o = 16; o; o >>= 1) z += __shfl_xor_sync(0xffffffffu, z, o);
    float zinv = (float)S / (z + EPS);

    float acc = 0.f;
#pragma unroll
    for (int d = 0; d < 32; d++)
        acc += __shfl_sync(0xffffffffu, qf, d) * sKV[d][lane];

    O[ro + lane] = __float2half(acc * zinv);
}

// ---------------- launch ----------------
extern "C" void kernel_launch(void* const* d_in, const int* in_sizes, int n_in,
                              void* d_out, int out_size)
{
    const float* q   = (const float*)d_in[0];
    const float* k   = (const float*)d_in[1];
    const float* v   = (const float*)d_in[2];
    const void*  qmask = d_in[3];
    const void*  kmask = d_in[4];
    const float* Wq  = (const float*)d_in[5];
    const float* bq  = (const float*)d_in[6];
    const float* Wk  = (const float*)d_in[7];
    const float* bk  = (const float*)d_in[8];
    const float* Wv  = (const float*)d_in[9];
    const float* bv  = (const float*)d_in[10];
    const float* Wm  = (const float*)d_in[11];
    float* out = (float*)d_out;

    float*  g_qm_p; cudaGetSymbolAddress((void**)&g_qm_p, g_qm);
    float*  g_km_p; cudaGetSymbolAddress((void**)&g_km_p, g_km);
    __half* g_Qf_p; cudaGetSymbolAddress((void**)&g_Qf_p, g_Qf);
    __half* g_Kf_p; cudaGetSymbolAddress((void**)&g_Kf_p, g_Kf);
    __half* g_Vm_p; cudaGetSymbolAddress((void**)&g_Vm_p, g_Vm);
    __half* g_Oh_p; cudaGetSymbolAddress((void**)&g_Oh_p, g_Oh);
    __half* g_qh_p; cudaGetSymbolAddress((void**)&g_qh_p, g_qh);
    __half* g_kh_p; cudaGetSymbolAddress((void**)&g_kh_p, g_kh);
    __half* g_vh_p; cudaGetSymbolAddress((void**)&g_vh_p, g_vh);
    __half* g_Wh_p; cudaGetSymbolAddress((void**)&g_Wh_p, g_Wh);

    static bool attr_set = false;
    if (!attr_set) {
        cudaFuncSetAttribute(gemm_f16, cudaFuncAttributeMaxDynamicSharedMemorySize, GEMM_DSMEM);
        attr_set = true;
    }

    // 1) mask detect/convert + fp16 conversions
    detect_mask_kernel<<<1, 256>>>(qmask);
    convert_mask_kernel<<<(NL + 255) / 256, 256>>>(qmask, g_qm_p, NL);
    convert_mask_kernel<<<(NS + 255) / 256, 256>>>(kmask, g_km_p, NS);
    dim3 cgrid((NL * E / 8 + 255) / 256, 3);
    cvt_inputs_kernel<<<cgrid, 256>>>(q, k, v, g_qh_p, g_kh_p, g_vh_p);
    dim3 wgrid((E * E / 8 + 255) / 256, 4);
    cvt_weights_kernel<<<wgrid, 256>>>(Wq, Wk, Wv, Wm);

    // 2) fused QKV projections (fp16 in, fp16 out)
    dim3 ggrid(E / BN, NL / BM);
    gemm_f16<<<ggrid, 256, GEMM_DSMEM>>>(g_qh_p, g_Wh_p + 0 * (size_t)E * E, bq, g_Qf_p, g_qm_p, 1.0f, 1, 1);
    gemm_f16<<<ggrid, 256, GEMM_DSMEM>>>(g_kh_p, g_Wh_p + 1 * (size_t)E * E, bk, g_Kf_p, g_km_p, 1.0f, 1, 1);
    gemm_f16<<<ggrid, 256, GEMM_DSMEM>>>(g_vh_p, g_Wh_p + 2 * (size_t)E * E, bv, g_Vm_p, g_km_p, 1.0f / (float)S, 2, 1);

    // 3) KV aggregation (s-split) + reduction
    dim3 kvgrid(NB * H, KV_SPLIT);
    kv_agg_kernel<<<kvgrid, 256>>>(g_Kf_p, g_Vm_p);
    kv_reduce_kernel<<<(NB * H * D * D + NB * H * D + 255) / 256, 256>>>();

    // 4) attention apply (fp16 in/out)
    attn_kernel<<<NB * H * (L / 8), 256>>>(g_Qf_p, g_Oh_p);

    // 5) merge projection (fp16 in, fp32 out)
    gemm_f16<<<ggrid, 256, GEMM_DSMEM>>>(g_Oh_p, g_Wh_p + 3 * (size_t)E * E, nullptr, out, nullptr, 1.0f, 0, 0);
}

// round 15
// speedup vs baseline: 1.0917x; 1.0917x over previous
#include <cuda_runtime.h>
#include <cuda_fp16.h>
#include <math.h>
#include <stdint.h>

// Problem constants
constexpr int NB = 8;
constexpr int L  = 4096;
constexpr int S  = 4096;
constexpr int E  = 256;
constexpr int H  = 8;
constexpr int D  = 32;
constexpr int NL = NB * L;   // 32768
constexpr int NS = NB * S;   // 32768
constexpr float EPS = 1e-6f;
constexpr int KV_SPLIT = 8;

// ---------------- scratch (device globals; no allocation allowed) ----------------
__device__ __half g_Qf[(size_t)NL * E];
__device__ __half g_Kf[(size_t)NS * E];
__device__ __half g_Vm[(size_t)NS * E];
__device__ __half g_Oh[(size_t)NL * E];
__device__ __half g_qh[(size_t)NL * E];
__device__ __half g_kh[(size_t)NS * E];
__device__ __half g_vh[(size_t)NS * E];
__device__ __half g_Wh[4][(size_t)E * E];
__device__ float  g_KV[(size_t)NB * H * D * D];
__device__ float  g_Ksum[(size_t)NB * H * D];
__device__ float  g_KVp[KV_SPLIT][(size_t)NB * H * D * D];
__device__ float  g_Ksump[KV_SPLIT][(size_t)NB * H * D];
__device__ int    g_mask_mode;

// ---------------- helpers ----------------
__device__ __forceinline__ uint32_t smem_u32(const void* p) {
    uint32_t r;
    asm("{ .reg .u64 t; cvta.to.shared.u64 t, %1; cvt.u32.u64 %0, t; }" : "=r"(r) : "l"(p));
    return r;
}

__device__ __forceinline__ uint32_t pack_h2(float x, float y) {
    __half2 h = __floats2half2_rn(x, y);
    return *(uint32_t*)&h;
}

__device__ __forceinline__ void ldmx4(uint32_t (&r)[4], uint32_t addr) {
    asm volatile("ldmatrix.sync.aligned.m8n8.x4.shared.b16 {%0,%1,%2,%3}, [%4];"
                 : "=r"(r[0]), "=r"(r[1]), "=r"(r[2]), "=r"(r[3]) : "r"(addr));
}

__device__ __forceinline__ void mma_f16(float (&d)[4], const uint32_t (&a)[4],
                                        uint32_t b0, uint32_t b1) {
    asm volatile(
        "mma.sync.aligned.m16n8k16.row.col.f32.f16.f16.f32 "
        "{%0,%1,%2,%3}, {%4,%5,%6,%7}, {%8,%9}, {%0,%1,%2,%3};"
        : "+f"(d[0]), "+f"(d[1]), "+f"(d[2]), "+f"(d[3])
        : "r"(a[0]), "r"(a[1]), "r"(a[2]), "r"(a[3]), "r"(b0), "r"(b1));
}

__device__ __forceinline__ void cp_async16(uint32_t dst, const void* src) {
    asm volatile("cp.async.cg.shared.global [%0], [%1], 16;" :: "r"(dst), "l"(src) : "memory");
}
__device__ __forceinline__ void cp_commit() {
    asm volatile("cp.async.commit_group;" ::: "memory");
}
__device__ __forceinline__ void cp_wait2() {
    asm volatile("cp.async.wait_group 2;" ::: "memory");
}

// raw mask element -> 0/1 float (mode from g_mask_mode)
__device__ __forceinline__ float mask_val(const void* m, int i, int mode) {
    if (mode == 0) return ((const unsigned char*)m)[i] ? 1.f : 0.f;
    if (mode == 1) return ((const int*)m)[i] ? 1.f : 0.f;
    return (((const float*)m)[i] != 0.f) ? 1.f : 0.f;
}

// ---------------- mask dtype detection ----------------
__global__ void detect_mask_kernel(const void* mask) {
    __shared__ int s_off1, s_3f;
    const int tid = threadIdx.x;
    if (tid == 0) { s_off1 = 0; s_3f = 0; }
    __syncthreads();
    unsigned char c = ((const unsigned char*)mask)[tid];
    if ((tid & 3) == 1 && c == 1) atomicOr(&s_off1, 1);
    if (c == 0x3F)                atomicOr(&s_3f, 1);
    __syncthreads();
    if (tid == 0) g_mask_mode = s_off1 ? 0 : (s_3f ? 2 : 1);
}

// ---------------- fp32 -> fp16 conversion (inputs + weights) ----------------
__global__ void cvt_inputs_kernel(const float* __restrict__ a, const float* __restrict__ b,
                                  const float* __restrict__ c,
                                  __half* __restrict__ da, __half* __restrict__ db,
                                  __half* __restrict__ dc) {
    const int seg = blockIdx.y;
    const float* s = (seg == 0) ? a : (seg == 1) ? b : c;
    __half*      d = (seg == 0) ? da : (seg == 1) ? db : dc;
    size_t i = ((size_t)blockIdx.x * blockDim.x + threadIdx.x) * 8;
    float4 f0 = *(const float4*)&s[i];
    float4 f1 = *(const float4*)&s[i + 4];
    uint4 o = make_uint4(pack_h2(f0.x, f0.y), pack_h2(f0.z, f0.w),
                         pack_h2(f1.x, f1.y), pack_h2(f1.z, f1.w));
    *(uint4*)&d[i] = o;
}

__global__ void cvt_weights_kernel(const float* __restrict__ w0, const float* __restrict__ w1,
                                   const float* __restrict__ w2, const float* __restrict__ w3) {
    const int seg = blockIdx.y;
    const float* s = (seg == 0) ? w0 : (seg == 1) ? w1 : (seg == 2) ? w2 : w3;
    __half*      d = g_Wh[seg];
    size_t i = ((size_t)blockIdx.x * blockDim.x + threadIdx.x) * 8;
    float4 f0 = *(const float4*)&s[i];
    float4 f1 = *(const float4*)&s[i + 4];
    uint4 o = make_uint4(pack_h2(f0.x, f0.y), pack_h2(f0.z, f0.w),
                         pack_h2(f1.x, f1.y), pack_h2(f1.z, f1.w));
    *(uint4*)&d[i] = o;
}

// ---------------- fp16 tensor-core GEMM core ----------------
// C = A @ W^T (+bias); mode 0: plain   1: (elu+1)*mask   2: x*mask*scale
// outhalf: 0 -> float* C, 1 -> __half* C.  mask is RAW (converted inline).
#define BM 128
#define BN 128
#define BK 32
#define BUFB 8192
#define NSTAGE 4
constexpr int GEMM_DSMEM = 2 * NSTAGE * BUFB;   // 64KB

__device__ __forceinline__ void gemm_core(
    const __half* __restrict__ A, const __half* __restrict__ W,
    const float* __restrict__ bias, void* __restrict__ Cv,
    const void* __restrict__ mask, float scale, int mode, int outhalf,
    int m0, int n0, unsigned char* dynsm)
{
    const uint32_t sA = smem_u32(dynsm);
    const uint32_t sB = sA + NSTAGE * BUFB;

    const int tid  = threadIdx.x;
    const int wid  = tid >> 5;
    const int lane = tid & 31;
    const int wm   = (wid & 1) * 64;
    const int wn   = (wid >> 1) * 32;
    const int g    = lane >> 2;
    const int tg   = lane & 3;

    // fill indices
    int fr[2], fc[2];
    uint32_t foff[2];
#pragma unroll
    for (int p = 0; p < 2; p++) {
        int idx = p * 256 + tid;
        fr[p] = idx >> 2;
        fc[p] = idx & 3;
        foff[p] = (uint32_t)(fr[p] * 64 + ((fc[p] ^ ((fr[p] >> 1) & 3)) << 4));
    }

    // ldmatrix addresses
    uint32_t adA[4][2], adB[2][2];
#pragma unroll
    for (int i = 0; i < 4; i++) {
        int r = wm + i * 16 + ((lane >> 3) & 1) * 8 + (lane & 7);
#pragma unroll
        for (int s = 0; s < 2; s++) {
            int kc = 2 * s + (lane >> 4);
            adA[i][s] = sA + (uint32_t)(r * 64 + ((kc ^ ((r >> 1) & 3)) << 4));
        }
    }
#pragma unroll
    for (int jp = 0; jp < 2; jp++) {
        int r = wn + (2 * jp + ((lane >> 3) >> 1)) * 8 + (lane & 7);
#pragma unroll
        for (int s = 0; s < 2; s++) {
            int kc = 2 * s + ((lane >> 3) & 1);
            adB[jp][s] = sB + (uint32_t)(r * 64 + ((kc ^ ((r >> 1) & 3)) << 4));
        }
    }

    float acc[4][4][4];
#pragma unroll
    for (int i = 0; i < 4; i++)
#pragma unroll
        for (int j = 0; j < 4; j++)
#pragma unroll
            for (int r = 0; r < 4; r++) acc[i][j][r] = 0.f;

    auto issue_stage = [&](int s) {
        const uint32_t so = (uint32_t)(s & 3) * BUFB;
#pragma unroll
        for (int p = 0; p < 2; p++) {
            const __half* srcA = A + (size_t)(m0 + fr[p]) * E + s * BK + fc[p] * 8;
            cp_async16(sA + so + foff[p], srcA);
            const __half* srcB = W + (size_t)(n0 + fr[p]) * E + s * BK + fc[p] * 8;
            cp_async16(sB + so + foff[p], srcB);
        }
    };

    issue_stage(0); cp_commit();
    issue_stage(1); cp_commit();
    issue_stage(2); cp_commit();

    constexpr int NITER = E / BK;   // 8
#pragma unroll
    for (int c = 0; c < NITER; c++) {
        cp_wait2();
        __syncthreads();
        if (c + 3 < NITER) issue_stage(c + 3);
        cp_commit();

        const uint32_t boff = (uint32_t)(c & 3) * BUFB;
#pragma unroll
        for (int s = 0; s < 2; s++) {
            uint32_t a[4][4];
#pragma unroll
            for (int i = 0; i < 4; i++) ldmx4(a[i], adA[i][s] + boff);
            uint32_t bb[2][4];
#pragma unroll
            for (int jp = 0; jp < 2; jp++) ldmx4(bb[jp], adB[jp][s] + boff);
#pragma unroll
            for (int i = 0; i < 4; i++) {
#pragma unroll
                for (int j = 0; j < 4; j++) {
                    const int jp = j >> 1, hi = j & 1;
                    mma_f16(acc[i][j], a[i], bb[jp][hi * 2], bb[jp][hi * 2 + 1]);
                }
            }
        }
    }

    // epilogue
    const int mmode = (mode != 0) ? g_mask_mode : 0;
    float*  Cf = (float*)Cv;
    __half* Ch = (__half*)Cv;
#pragma unroll
    for (int i = 0; i < 4; i++) {
        const int r0 = m0 + wm + i * 16 + g;
        const int r1 = r0 + 8;
        float rm0 = 0.f, rm1 = 0.f;
        if (mode != 0) { rm0 = mask_val(mask, r0, mmode); rm1 = mask_val(mask, r1, mmode); }
#pragma unroll
        for (int j = 0; j < 4; j++) {
            const int col = n0 + wn + j * 8 + 2 * tg;
            float b0 = 0.f, b1 = 0.f;
            if (bias) { b0 = bias[col]; b1 = bias[col + 1]; }
            float v0 = acc[i][j][0] + b0;
            float v1 = acc[i][j][1] + b1;
            float v2 = acc[i][j][2] + b0;
            float v3 = acc[i][j][3] + b1;
            if (mode == 1) {
                v0 = ((v0 > 0.f) ? (v0 + 1.f) : expf(v0)) * rm0;
                v1 = ((v1 > 0.f) ? (v1 + 1.f) : expf(v1)) * rm0;
                v2 = ((v2 > 0.f) ? (v2 + 1.f) : expf(v2)) * rm1;
                v3 = ((v3 > 0.f) ? (v3 + 1.f) : expf(v3)) * rm1;
            } else if (mode == 2) {
                v0 *= rm0 * scale; v1 *= rm0 * scale;
                v2 *= rm1 * scale; v3 *= rm1 * scale;
            }
            if (outhalf) {
                *(uint32_t*)&Ch[(size_t)r0 * E + col] = pack_h2(v0, v1);
                *(uint32_t*)&Ch[(size_t)r1 * E + col] = pack_h2(v2, v3);
            } else {
                *(float2*)&Cf[(size_t)r0 * E + col] = make_float2(v0, v1);
                *(float2*)&Cf[(size_t)r1 * E + col] = make_float2(v2, v3);
            }
        }
    }
}

// batched QKV projection: blockIdx.z selects {q,k,v}
__global__ __launch_bounds__(256, 2)
void gemm_qkv(const __half* __restrict__ Aq, const __half* __restrict__ Ak,
              const __half* __restrict__ Av, const __half* __restrict__ Wbase,
              const float* __restrict__ bq, const float* __restrict__ bk,
              const float* __restrict__ bv,
              __half* __restrict__ Cq, __half* __restrict__ Ck, __half* __restrict__ Cv_,
              const void* __restrict__ qmask, const void* __restrict__ kmask)
{
    extern __shared__ __align__(16) unsigned char dynsm[];
    const int z = blockIdx.z;
    const __half* A    = (z == 0) ? Aq : (z == 1) ? Ak : Av;
    const __half* W    = Wbase + (size_t)z * E * E;
    const float*  bias = (z == 0) ? bq : (z == 1) ? bk : bv;
    __half*       C    = (z == 0) ? Cq : (z == 1) ? Ck : Cv_;
    const void*   mask = (z == 0) ? qmask : kmask;
    const float   scale = (z == 2) ? (1.0f / (float)S) : 1.0f;
    const int     mode  = (z == 2) ? 2 : 1;
    gemm_core(A, W, bias, C, mask, scale, mode, 1,
              blockIdx.y * BM, blockIdx.x * BN, dynsm);
}

// merge projection: fp16 in, fp32 out, no bias/mask
__global__ __launch_bounds__(256, 2)
void gemm_merge(const __half* __restrict__ A, const __half* __restrict__ W,
                float* __restrict__ C)
{
    extern __shared__ __align__(16) unsigned char dynsm[];
    gemm_core(A, W, nullptr, C, nullptr, 1.0f, 0, 0,
              blockIdx.y * BM, blockIdx.x * BN, dynsm);
}

// ---------------- KV aggregation (s-split, fp16 in, R13 loader mapping) ----------------
__global__ __launch_bounds__(256)
void kv_agg_kernel(const __half* __restrict__ Kf, const __half* __restrict__ Vm)
{
    const int n = blockIdx.x >> 3;
    const int h = blockIdx.x & 7;
    const int split = blockIdx.y;
    const int sbeg = split * (S / KV_SPLIT);
    const int send = sbeg + (S / KV_SPLIT);

    __shared__ float sK[64][40];
    __shared__ float sV[64][40];
    __shared__ float red[4][64][16];

    const int tid = threadIdx.x;
    const int g = tid >> 6;
    const int t = tid & 63;
    const int db = (t >> 3) << 2;
    const int vb = (t & 7) << 2;

    // R13 loader mapping: float4 smem stores (conflict-free), 8B fp16 global loads
    const int lr = tid >> 3;            // 0..31
    const int lc = (tid & 7) << 2;      // 0,4,...,28

    float acc[4][4];
#pragma unroll
    for (int i = 0; i < 4; i++)
#pragma unroll
        for (int j = 0; j < 4; j++) acc[i][j] = 0.f;
    float ksum = 0.f;

    const size_t base = (size_t)n * S * E + (size_t)h * D;

    for (int s0 = sbeg; s0 < send; s0 += 64) {
#pragma unroll
        for (int p = 0; p < 2; p++) {
            int r = lr + p * 32;
            size_t off = base + (size_t)(s0 + r) * E + lc;
            uint2 kr = *(const uint2*)&Kf[off];
            uint2 vr = *(const uint2*)&Vm[off];
            float2 k0 = __half22float2(*(const __half2*)&kr.x);
            float2 k1 = __half22float2(*(const __half2*)&kr.y);
            float2 v0 = __half22float2(*(const __half2*)&vr.x);
            float2 v1 = __half22float2(*(const __half2*)&vr.y);
            *(float4*)&sK[r][lc] = make_float4(k0.x, k0.y, k1.x, k1.y);
            *(float4*)&sV[r][lc] = make_float4(v0.x, v0.y, v1.x, v1.y);
        }
        __syncthreads();

        for (int ss = g; ss < 64; ss += 4) {
            float4 k4 = *(const float4*)&sK[ss][db];
            float4 v4 = *(const float4*)&sV[ss][vb];
            acc[0][0] += k4.x * v4.x; acc[0][1] += k4.x * v4.y; acc[0][2] += k4.x * v4.z; acc[0][3] += k4.x * v4.w;
            acc[1][0] += k4.y * v4.x; acc[1][1] += k4.y * v4.y; acc[1][2] += k4.y * v4.z; acc[1][3] += k4.y * v4.w;
            acc[2][0] += k4.z * v4.x; acc[2][1] += k4.z * v4.y; acc[2][2] += k4.z * v4.z; acc[2][3] += k4.z * v4.w;
            acc[3][0] += k4.w * v4.x; acc[3][1] += k4.w * v4.y; acc[3][2] += k4.w * v4.z; acc[3][3] += k4.w * v4.w;
        }
        if (g == 0 && t < 32) {
#pragma unroll
            for (int ss = 0; ss < 64; ss++) ksum += sK[ss][t];
        }
        __syncthreads();
    }

#pragma unroll
    for (int jd = 0; jd < 4; jd++)
#pragma unroll
        for (int jv = 0; jv < 4; jv++) red[g][t][jd * 4 + jv] = acc[jd][jv];
    __syncthreads();

    const size_t kvbase = (size_t)((n * H + h) * D) * D;
#pragma unroll
    for (int q = 0; q < 4; q++) {
        int o = tid * 4 + q;
        int d = o >> 5, v = o & 31;
        int tt = ((d >> 2) << 3) | (v >> 2);
        int jj = ((d & 3) << 2) | (v & 3);
        float val = red[0][tt][jj] + red[1][tt][jj] + red[2][tt][jj] + red[3][tt][jj];
        g_KVp[split][kvbase + (size_t)d * D + v] = val;
    }
    if (g == 0 && t < 32) g_Ksump[split][(size_t)(n * H + h) * D + t] = ksum;
}

// ---------------- KV partial reduction ----------------
__global__ void kv_reduce_kernel() {
    const int NKV = NB * H * D * D;
    const int NKS = NB * H * D;
    int i = blockIdx.x * blockDim.x + threadIdx.x;
    if (i < NKV) {
        float s = 0.f;
#pragma unroll
        for (int p = 0; p < KV_SPLIT; p++) s += g_KVp[p][i];
        g_KV[i] = s;
    } else if (i < NKV + NKS) {
        int j = i - NKV;
        float s = 0.f;
#pragma unroll
        for (int p = 0; p < KV_SPLIT; p++) s += g_Ksump[p][j];
        g_Ksum[j] = s;
    }
}

// ---------------- attention apply: Oh = fp16( (Qf @ KV) * Z * S ) ----------------
__global__ __launch_bounds__(256)
void attn_kernel(const __half* __restrict__ Qf, __half* __restrict__ O)
{
    const int bid  = blockIdx.x;
    const int n    = bid >> 12;
    const int h    = (bid >> 9) & 7;
    const int lgrp = bid & 511;

    __shared__ float sKV[32][32];
    __shared__ float sKs[32];

    const int tid = threadIdx.x;
    const float* kvp = g_KV + (size_t)((n * H + h) * D) * D;
    ((float4*)sKV)[tid] = ((const float4*)kvp)[tid];
    if (tid < 32) sKs[tid] = g_Ksum[(size_t)(n * H + h) * D + tid];
    __syncthreads();

    const int w = tid >> 5, lane = tid & 31;
    const int l = (lgrp << 3) | w;
    const size_t ro = ((size_t)n * L + l) * E + (size_t)h * D;

    float qf = __half2float(Qf[ro + lane]);
    float z = qf * sKs[lane];
#pragma unroll
    for (int o = 16; o; o >>= 1) z += __shfl_xor_sync(0xffffffffu, z, o);
    float zinv = (float)S / (z + EPS);

    float acc = 0.f;
#pragma unroll
    for (int d = 0; d < 32; d++)
        acc += __shfl_sync(0xffffffffu, qf, d) * sKV[d][lane];

    O[ro + lane] = __float2half(acc * zinv);
}

// ---------------- launch ----------------
extern "C" void kernel_launch(void* const* d_in, const int* in_sizes, int n_in,
                              void* d_out, int out_size)
{
    const float* q   = (const float*)d_in[0];
    const float* k   = (const float*)d_in[1];
    const float* v   = (const float*)d_in[2];
    const void*  qmask = d_in[3];
    const void*  kmask = d_in[4];
    const float* Wq  = (const float*)d_in[5];
    const float* bq  = (const float*)d_in[6];
    const float* Wk  = (const float*)d_in[7];
    const float* bk  = (const float*)d_in[8];
    const float* Wv  = (const float*)d_in[9];
    const float* bv  = (const float*)d_in[10];
    const float* Wm  = (const float*)d_in[11];
    float* out = (float*)d_out;

    __half* g_Qf_p; cudaGetSymbolAddress((void**)&g_Qf_p, g_Qf);
    __half* g_Kf_p; cudaGetSymbolAddress((void**)&g_Kf_p, g_Kf);
    __half* g_Vm_p; cudaGetSymbolAddress((void**)&g_Vm_p, g_Vm);
    __half* g_Oh_p; cudaGetSymbolAddress((void**)&g_Oh_p, g_Oh);
    __half* g_qh_p; cudaGetSymbolAddress((void**)&g_qh_p, g_qh);
    __half* g_kh_p; cudaGetSymbolAddress((void**)&g_kh_p, g_kh);
    __half* g_vh_p; cudaGetSymbolAddress((void**)&g_vh_p, g_vh);
    __half* g_Wh_p; cudaGetSymbolAddress((void**)&g_Wh_p, g_Wh);

    static bool attr_set = false;
    if (!attr_set) {
        cudaFuncSetAttribute(gemm_qkv,   cudaFuncAttributeMaxDynamicSharedMemorySize, GEMM_DSMEM);
        cudaFuncSetAttribute(gemm_merge, cudaFuncAttributeMaxDynamicSharedMemorySize, GEMM_DSMEM);
        attr_set = true;
    }

    // 1) mask detect + fp16 conversions
    detect_mask_kernel<<<1, 256>>>(qmask);
    dim3 cgrid((NL * E / 8 + 255) / 256, 3);
    cvt_inputs_kernel<<<cgrid, 256>>>(q, k, v, g_qh_p, g_kh_p, g_vh_p);
    dim3 wgrid((E * E / 8 + 255) / 256, 4);
    cvt_weights_kernel<<<wgrid, 256>>>(Wq, Wk, Wv, Wm);

    // 2) batched QKV projections (fp16 in/out, mask fused in epilogue)
    dim3 ggrid(E / BN, NL / BM, 3);
    gemm_qkv<<<ggrid, 256, GEMM_DSMEM>>>(g_qh_p, g_kh_p, g_vh_p, g_Wh_p,
                                         bq, bk, bv,
                                         g_Qf_p, g_Kf_p, g_Vm_p,
                                         qmask, kmask);

    // 3) KV aggregation (s-split) + reduction
    dim3 kvgrid(NB * H, KV_SPLIT);
    kv_agg_kernel<<<kvgrid, 256>>>(g_Kf_p, g_Vm_p);
    kv_reduce_kernel<<<(NB * H * D * D + NB * H * D + 255) / 256, 256>>>();

    // 4) attention apply (fp16 in/out)
    attn_kernel<<<NB * H * (L / 8), 256>>>(g_Qf_p, g_Oh_p);

    // 5) merge projection (fp16 in, fp32 out)
    dim3 mgrid(E / BN, NL / BM);
    gemm_merge<<<mgrid, 256, GEMM_DSMEM>>>(g_Oh_p, g_Wh_p + 3 * (size_t)E * E, out);
}

// round 16
// speedup vs baseline: 1.1032x; 1.0106x over previous
#include <cuda_runtime.h>
#include <cuda_fp16.h>
#include <math.h>
#include <stdint.h>

// Problem constants
constexpr int NB = 8;
constexpr int L  = 4096;
constexpr int S  = 4096;
constexpr int E  = 256;
constexpr int H  = 8;
constexpr int D  = 32;
constexpr int NL = NB * L;   // 32768
constexpr int NS = NB * S;   // 32768
constexpr float EPS = 1e-6f;
constexpr int KV_SPLIT = 8;

// ---------------- scratch (device globals; no allocation allowed) ----------------
__device__ __half g_Qf[(size_t)NL * E];
__device__ __half g_Kf[(size_t)NS * E];
__device__ __half g_Vm[(size_t)NS * E];
__device__ __half g_Oh[(size_t)NL * E];
__device__ __half g_qh[(size_t)NL * E];
__device__ __half g_kh[(size_t)NS * E];
__device__ __half g_vh[(size_t)NS * E];
__device__ __half g_Wh[4][(size_t)E * E];
__device__ float  g_KV[(size_t)NB * H * D * D];
__device__ float  g_Ksum[(size_t)NB * H * D];
__device__ float  g_KVp[KV_SPLIT][(size_t)NB * H * D * D];
__device__ float  g_Ksump[KV_SPLIT][(size_t)NB * H * D];
__device__ int    g_mask_mode;

// ---------------- helpers ----------------
__device__ __forceinline__ uint32_t smem_u32(const void* p) {
    uint32_t r;
    asm("{ .reg .u64 t; cvta.to.shared.u64 t, %1; cvt.u32.u64 %0, t; }" : "=r"(r) : "l"(p));
    return r;
}

__device__ __forceinline__ uint32_t pack_h2(float x, float y) {
    __half2 h = __floats2half2_rn(x, y);
    return *(uint32_t*)&h;
}

__device__ __forceinline__ void ldmx4(uint32_t (&r)[4], uint32_t addr) {
    asm volatile("ldmatrix.sync.aligned.m8n8.x4.shared.b16 {%0,%1,%2,%3}, [%4];"
                 : "=r"(r[0]), "=r"(r[1]), "=r"(r[2]), "=r"(r[3]) : "r"(addr));
}

__device__ __forceinline__ void mma_f16(float (&d)[4], const uint32_t (&a)[4],
                                        uint32_t b0, uint32_t b1) {
    asm volatile(
        "mma.sync.aligned.m16n8k16.row.col.f32.f16.f16.f32 "
        "{%0,%1,%2,%3}, {%4,%5,%6,%7}, {%8,%9}, {%0,%1,%2,%3};"
        : "+f"(d[0]), "+f"(d[1]), "+f"(d[2]), "+f"(d[3])
        : "r"(a[0]), "r"(a[1]), "r"(a[2]), "r"(a[3]), "r"(b0), "r"(b1));
}

__device__ __forceinline__ void cp_async16(uint32_t dst, const void* src) {
    asm volatile("cp.async.cg.shared.global [%0], [%1], 16;" :: "r"(dst), "l"(src) : "memory");
}
__device__ __forceinline__ void cp_commit() {
    asm volatile("cp.async.commit_group;" ::: "memory");
}
__device__ __forceinline__ void cp_wait1() {
    asm volatile("cp.async.wait_group 1;" ::: "memory");
}

// raw mask element -> 0/1 float (mode from g_mask_mode)
__device__ __forceinline__ float mask_val(const void* m, int i, int mode) {
    if (mode == 0) return ((const unsigned char*)m)[i] ? 1.f : 0.f;
    if (mode == 1) return ((const int*)m)[i] ? 1.f : 0.f;
    return (((const float*)m)[i] != 0.f) ? 1.f : 0.f;
}

// ---------------- mask dtype detection ----------------
__global__ void detect_mask_kernel(const void* mask) {
    __shared__ int s_off1, s_3f;
    const int tid = threadIdx.x;
    if (tid == 0) { s_off1 = 0; s_3f = 0; }
    __syncthreads();
    unsigned char c = ((const unsigned char*)mask)[tid];
    if ((tid & 3) == 1 && c == 1) atomicOr(&s_off1, 1);
    if (c == 0x3F)                atomicOr(&s_3f, 1);
    __syncthreads();
    if (tid == 0) g_mask_mode = s_off1 ? 0 : (s_3f ? 2 : 1);
}

// ---------------- fp32 -> fp16 conversion (inputs + weights) ----------------
__global__ void cvt_inputs_kernel(const float* __restrict__ a, const float* __restrict__ b,
                                  const float* __restrict__ c,
                                  __half* __restrict__ da, __half* __restrict__ db,
                                  __half* __restrict__ dc) {
    const int seg = blockIdx.y;
    const float* s = (seg == 0) ? a : (seg == 1) ? b : c;
    __half*      d = (seg == 0) ? da : (seg == 1) ? db : dc;
    size_t i = ((size_t)blockIdx.x * blockDim.x + threadIdx.x) * 8;
    float4 f0 = *(const float4*)&s[i];
    float4 f1 = *(const float4*)&s[i + 4];
    uint4 o = make_uint4(pack_h2(f0.x, f0.y), pack_h2(f0.z, f0.w),
                         pack_h2(f1.x, f1.y), pack_h2(f1.z, f1.w));
    *(uint4*)&d[i] = o;
}

__global__ void cvt_weights_kernel(const float* __restrict__ w0, const float* __restrict__ w1,
                                   const float* __restrict__ w2, const float* __restrict__ w3) {
    const int seg = blockIdx.y;
    const float* s = (seg == 0) ? w0 : (seg == 1) ? w1 : (seg == 2) ? w2 : w3;
    __half*      d = g_Wh[seg];
    size_t i = ((size_t)blockIdx.x * blockDim.x + threadIdx.x) * 8;
    float4 f0 = *(const float4*)&s[i];
    float4 f1 = *(const float4*)&s[i + 4];
    uint4 o = make_uint4(pack_h2(f0.x, f0.y), pack_h2(f0.z, f0.w),
                         pack_h2(f1.x, f1.y), pack_h2(f1.z, f1.w));
    *(uint4*)&d[i] = o;
}

// ---------------- fp16 tensor-core GEMM core (BK=64, 3-stage cp.async) ----------------
// C = A @ W^T (+bias); mode 0: plain   1: (elu+1)*mask   2: x*mask*scale
// outhalf: 0 -> float* C, 1 -> __half* C.  mask is RAW (converted inline).
// SMEM per matrix per stage: 128 rows x 128B; 16B chunk c8 of row r at
// r*128 + ((c8 ^ (r&7))<<4)  -- conflict-free cp.async fill + ldmatrix.
#define BM 128
#define BN 128
#define BK 64
#define BUFB 16384
#define NSTAGE 3
constexpr int GEMM_DSMEM = 2 * NSTAGE * BUFB;   // 96KB

__device__ __forceinline__ void gemm_core(
    const __half* __restrict__ A, const __half* __restrict__ W,
    const float* __restrict__ bias, void* __restrict__ Cv,
    const void* __restrict__ mask, float scale, int mode, int outhalf,
    int m0, int n0, unsigned char* dynsm)
{
    const uint32_t sA = smem_u32(dynsm);
    const uint32_t sB = sA + NSTAGE * BUFB;

    const int tid  = threadIdx.x;
    const int wid  = tid >> 5;
    const int lane = tid & 31;
    const int wm   = (wid & 1) * 64;
    const int wn   = (wid >> 1) * 32;
    const int g    = lane >> 2;
    const int tg   = lane & 3;

    // fill indices: 4 chunks per thread per matrix per stage (128 rows x 8 chunks)
    int fr[4], fc[4];
    uint32_t foff[4];
#pragma unroll
    for (int p = 0; p < 4; p++) {
        int idx = p * 256 + tid;
        fr[p] = idx >> 3;
        fc[p] = idx & 7;
        foff[p] = (uint32_t)(fr[p] * 128 + ((fc[p] ^ (fr[p] & 7)) << 4));
    }

    // ldmatrix row bases (swizzle applied inline per k-step)
    const int hA = lane >> 4;           // A k-chunk half (0/1)
    const int hB = (lane >> 3) & 1;     // B k-chunk half (0/1)
    uint32_t rbA[4]; int rxA[4];
#pragma unroll
    for (int i = 0; i < 4; i++) {
        int r = wm + i * 16 + (lane & 15);
        rbA[i] = sA + (uint32_t)(r * 128);
        rxA[i] = r & 7;
    }
    uint32_t rbB[2]; int rxB[2];
#pragma unroll
    for (int jp = 0; jp < 2; jp++) {
        int r = wn + (2 * jp + ((lane >> 3) >> 1)) * 8 + (lane & 7);
        rbB[jp] = sB + (uint32_t)(r * 128);
        rxB[jp] = r & 7;
    }

    float acc[4][4][4];
#pragma unroll
    for (int i = 0; i < 4; i++)
#pragma unroll
        for (int j = 0; j < 4; j++)
#pragma unroll
            for (int r = 0; r < 4; r++) acc[i][j][r] = 0.f;

    auto issue_stage = [&](int s) {
        const uint32_t so = (uint32_t)(s % NSTAGE) * BUFB;
#pragma unroll
        for (int p = 0; p < 4; p++) {
            const __half* srcA = A + (size_t)(m0 + fr[p]) * E + s * BK + fc[p] * 8;
            cp_async16(sA + so + foff[p], srcA);
            const __half* srcB = W + (size_t)(n0 + fr[p]) * E + s * BK + fc[p] * 8;
            cp_async16(sB + so + foff[p], srcB);
        }
    };

    issue_stage(0); cp_commit();
    issue_stage(1); cp_commit();

    constexpr int NITER = E / BK;   // 4
#pragma unroll
    for (int c = 0; c < NITER; c++) {
        cp_wait1();            // stage c complete (<=1 group pending)
        __syncthreads();
        if (c + 2 < NITER) issue_stage(c + 2);
        cp_commit();

        const uint32_t boff = (uint32_t)(c % NSTAGE) * BUFB;
#pragma unroll
        for (int s = 0; s < 4; s++) {   // 4 k16-steps per BK=64 tile
            uint32_t a[4][4];
#pragma unroll
            for (int i = 0; i < 4; i++) {
                int kc = 2 * s + hA;
                ldmx4(a[i], rbA[i] + boff + (uint32_t)((kc ^ rxA[i]) << 4));
            }
            uint32_t bb[2][4];
#pragma unroll
            for (int jp = 0; jp < 2; jp++) {
                int kc = 2 * s + hB;
                ldmx4(bb[jp], rbB[jp] + boff + (uint32_t)((kc ^ rxB[jp]) << 4));
            }
#pragma unroll
            for (int i = 0; i < 4; i++) {
#pragma unroll
                for (int j = 0; j < 4; j++) {
                    const int jp = j >> 1, hi = j & 1;
                    mma_f16(acc[i][j], a[i], bb[jp][hi * 2], bb[jp][hi * 2 + 1]);
                }
            }
        }
    }

    // epilogue
    const int mmode = (mode != 0) ? g_mask_mode : 0;
    float*  Cf = (float*)Cv;
    __half* Ch = (__half*)Cv;
#pragma unroll
    for (int i = 0; i < 4; i++) {
        const int r0 = m0 + wm + i * 16 + g;
        const int r1 = r0 + 8;
        float rm0 = 0.f, rm1 = 0.f;
        if (mode != 0) { rm0 = mask_val(mask, r0, mmode); rm1 = mask_val(mask, r1, mmode); }
#pragma unroll
        for (int j = 0; j < 4; j++) {
            const int col = n0 + wn + j * 8 + 2 * tg;
            float b0 = 0.f, b1 = 0.f;
            if (bias) { b0 = bias[col]; b1 = bias[col + 1]; }
            float v0 = acc[i][j][0] + b0;
            float v1 = acc[i][j][1] + b1;
            float v2 = acc[i][j][2] + b0;
            float v3 = acc[i][j][3] + b1;
            if (mode == 1) {
                v0 = ((v0 > 0.f) ? (v0 + 1.f) : expf(v0)) * rm0;
                v1 = ((v1 > 0.f) ? (v1 + 1.f) : expf(v1)) * rm0;
                v2 = ((v2 > 0.f) ? (v2 + 1.f) : expf(v2)) * rm1;
                v3 = ((v3 > 0.f) ? (v3 + 1.f) : expf(v3)) * rm1;
            } else if (mode == 2) {
                v0 *= rm0 * scale; v1 *= rm0 * scale;
                v2 *= rm1 * scale; v3 *= rm1 * scale;
            }
            if (outhalf) {
                *(uint32_t*)&Ch[(size_t)r0 * E + col] = pack_h2(v0, v1);
                *(uint32_t*)&Ch[(size_t)r1 * E + col] = pack_h2(v2, v3);
            } else {
                *(float2*)&Cf[(size_t)r0 * E + col] = make_float2(v0, v1);
                *(float2*)&Cf[(size_t)r1 * E + col] = make_float2(v2, v3);
            }
        }
    }
}

// batched QKV projection: blockIdx.z selects {q,k,v}
__global__ __launch_bounds__(256, 2)
void gemm_qkv(const __half* __restrict__ Aq, const __half* __restrict__ Ak,
              const __half* __restrict__ Av, const __half* __restrict__ Wbase,
              const float* __restrict__ bq, const float* __restrict__ bk,
              const float* __restrict__ bv,
              __half* __restrict__ Cq, __half* __restrict__ Ck, __half* __restrict__ Cv_,
              const void* __restrict__ qmask, const void* __restrict__ kmask)
{
    extern __shared__ __align__(16) unsigned char dynsm[];
    const int z = blockIdx.z;
    const __half* A    = (z == 0) ? Aq : (z == 1) ? Ak : Av;
    const __half* W    = Wbase + (size_t)z * E * E;
    const float*  bias = (z == 0) ? bq : (z == 1) ? bk : bv;
    __half*       C    = (z == 0) ? Cq : (z == 1) ? Ck : Cv_;
    const void*   mask = (z == 0) ? qmask : kmask;
    const float   scale = (z == 2) ? (1.0f / (float)S) : 1.0f;
    const int     mode  = (z == 2) ? 2 : 1;
    gemm_core(A, W, bias, C, mask, scale, mode, 1,
              blockIdx.y * BM, blockIdx.x * BN, dynsm);
}

// merge projection: fp16 in, fp32 out, no bias/mask
__global__ __launch_bounds__(256, 2)
void gemm_merge(const __half* __restrict__ A, const __half* __restrict__ W,
                float* __restrict__ C)
{
    extern __shared__ __align__(16) unsigned char dynsm[];
    gemm_core(A, W, nullptr, C, nullptr, 1.0f, 0, 0,
              blockIdx.y * BM, blockIdx.x * BN, dynsm);
}

// ---------------- KV aggregation (s-split, fp16 in) ----------------
__global__ __launch_bounds__(256)
void kv_agg_kernel(const __half* __restrict__ Kf, const __half* __restrict__ Vm)
{
    const int n = blockIdx.x >> 3;
    const int h = blockIdx.x & 7;
    const int split = blockIdx.y;
    const int sbeg = split * (S / KV_SPLIT);
    const int send = sbeg + (S / KV_SPLIT);

    __shared__ float sK[64][40];
    __shared__ float sV[64][40];
    __shared__ float red[4][64][16];

    const int tid = threadIdx.x;
    const int g = tid >> 6;
    const int t = tid & 63;
    const int db = (t >> 3) << 2;
    const int vb = (t & 7) << 2;

    const int lr = tid >> 3;            // 0..31
    const int lc = (tid & 7) << 2;      // 0,4,...,28

    float acc[4][4];
#pragma unroll
    for (int i = 0; i < 4; i++)
#pragma unroll
        for (int j = 0; j < 4; j++) acc[i][j] = 0.f;
    float ksum = 0.f;

    const size_t base = (size_t)n * S * E + (size_t)h * D;

    for (int s0 = sbeg; s0 < send; s0 += 64) {
#pragma unroll
        for (int p = 0; p < 2; p++) {
            int r = lr + p * 32;
            size_t off = base + (size_t)(s0 + r) * E + lc;
            uint2 kr = *(const uint2*)&Kf[off];
            uint2 vr = *(const uint2*)&Vm[off];
            float2 k0 = __half22float2(*(const __half2*)&kr.x);
            float2 k1 = __half22float2(*(const __half2*)&kr.y);
            float2 v0 = __half22float2(*(const __half2*)&vr.x);
            float2 v1 = __half22float2(*(const __half2*)&vr.y);
            *(float4*)&sK[r][lc] = make_float4(k0.x, k0.y, k1.x, k1.y);
            *(float4*)&sV[r][lc] = make_float4(v0.x, v0.y, v1.x, v1.y);
        }
        __syncthreads();

        for (int ss = g; ss < 64; ss += 4) {
            float4 k4 = *(const float4*)&sK[ss][db];
            float4 v4 = *(const float4*)&sV[ss][vb];
            acc[0][0] += k4.x * v4.x; acc[0][1] += k4.x * v4.y; acc[0][2] += k4.x * v4.z; acc[0][3] += k4.x * v4.w;
            acc[1][0] += k4.y * v4.x; acc[1][1] += k4.y * v4.y; acc[1][2] += k4.y * v4.z; acc[1][3] += k4.y * v4.w;
            acc[2][0] += k4.z * v4.x; acc[2][1] += k4.z * v4.y; acc[2][2] += k4.z * v4.z; acc[2][3] += k4.z * v4.w;
            acc[3][0] += k4.w * v4.x; acc[3][1] += k4.w * v4.y; acc[3][2] += k4.w * v4.z; acc[3][3] += k4.w * v4.w;
        }
        if (g == 0 && t < 32) {
#pragma unroll
            for (int ss = 0; ss < 64; ss++) ksum += sK[ss][t];
        }
        __syncthreads();
    }

#pragma unroll
    for (int jd = 0; jd < 4; jd++)
#pragma unroll
        for (int jv = 0; jv < 4; jv++) red[g][t][jd * 4 + jv] = acc[jd][jv];
    __syncthreads();

    const size_t kvbase = (size_t)((n * H + h) * D) * D;
#pragma unroll
    for (int q = 0; q < 4; q++) {
        int o = tid * 4 + q;
        int d = o >> 5, v = o & 31;
        int tt = ((d >> 2) << 3) | (v >> 2);
        int jj = ((d & 3) << 2) | (v & 3);
        float val = red[0][tt][jj] + red[1][tt][jj] + red[2][tt][jj] + red[3][tt][jj];
        g_KVp[split][kvbase + (size_t)d * D + v] = val;
    }
    if (g == 0 && t < 32) g_Ksump[split][(size_t)(n * H + h) * D + t] = ksum;
}

// ---------------- KV partial reduction ----------------
__global__ void kv_reduce_kernel() {
    const int NKV = NB * H * D * D;
    const int NKS = NB * H * D;
    int i = blockIdx.x * blockDim.x + threadIdx.x;
    if (i < NKV) {
        float s = 0.f;
#pragma unroll
        for (int p = 0; p < KV_SPLIT; p++) s += g_KVp[p][i];
        g_KV[i] = s;
    } else if (i < NKV + NKS) {
        int j = i - NKV;
        float s = 0.f;
#pragma unroll
        for (int p = 0; p < KV_SPLIT; p++) s += g_Ksump[p][j];
        g_Ksum[j] = s;
    }
}

// ---------------- attention apply: Oh = fp16( (Qf @ KV) * Z * S ) ----------------
__global__ __launch_bounds__(256)
void attn_kernel(const __half* __restrict__ Qf, __half* __restrict__ O)
{
    const int bid  = blockIdx.x;
    const int n    = bid >> 12;
    const int h    = (bid >> 9) & 7;
    const int lgrp = bid & 511;

    __shared__ float sKV[32][32];
    __shared__ float sKs[32];

    const int tid = threadIdx.x;
    const float* kvp = g_KV + (size_t)((n * H + h) * D) * D;
    ((float4*)sKV)[tid] = ((const float4*)kvp)[tid];
    if (tid < 32) sKs[tid] = g_Ksum[(size_t)(n * H + h) * D + tid];
    __syncthreads();

    const int w = tid >> 5, lane = tid & 31;
    const int l = (lgrp << 3) | w;
    const size_t ro = ((size_t)n * L + l) * E + (size_t)h * D;

    float qf = __half2float(Qf[ro + lane]);
    float z = qf * sKs[lane];
#pragma unroll
    for (int o = 16; o; o >>= 1) z += __shfl_xor_sync(0xffffffffu, z, o);
    float zinv = (float)S / (z + EPS);

    float acc = 0.f;
#pragma unroll
    for (int d = 0; d < 32; d++)
        acc += __shfl_sync(0xffffffffu, qf, d) * sKV[d][lane];

    O[ro + lane] = __float2half(acc * zinv);
}

// ---------------- launch ----------------
extern "C" void kernel_launch(void* const* d_in, const int* in_sizes, int n_in,
                              void* d_out, int out_size)
{
    const float* q   = (const float*)d_in[0];
    const float* k   = (const float*)d_in[1];
    const float* v   = (const float*)d_in[2];
    const void*  qmask = d_in[3];
    const void*  kmask = d_in[4];
    const float* Wq  = (const float*)d_in[5];
    const float* bq  = (const float*)d_in[6];
    const float* Wk  = (const float*)d_in[7];
    const float* bk  = (const float*)d_in[8];
    const float* Wv  = (const float*)d_in[9];
    const float* bv  = (const float*)d_in[10];
    const float* Wm  = (const float*)d_in[11];
    float* out = (float*)d_out;

    __half* g_Qf_p; cudaGetSymbolAddress((void**)&g_Qf_p, g_Qf);
    __half* g_Kf_p; cudaGetSymbolAddress((void**)&g_Kf_p, g_Kf);
    __half* g_Vm_p; cudaGetSymbolAddress((void**)&g_Vm_p, g_Vm);
    __half* g_Oh_p; cudaGetSymbolAddress((void**)&g_Oh_p, g_Oh);
    __half* g_qh_p; cudaGetSymbolAddress((void**)&g_qh_p, g_qh);
    __half* g_kh_p; cudaGetSymbolAddress((void**)&g_kh_p, g_kh);
    __half* g_vh_p; cudaGetSymbolAddress((void**)&g_vh_p, g_vh);
    __half* g_Wh_p; cudaGetSymbolAddress((void**)&g_Wh_p, g_Wh);

    static bool attr_set = false;
    if (!attr_set) {
        cudaFuncSetAttribute(gemm_qkv,   cudaFuncAttributeMaxDynamicSharedMemorySize, GEMM_DSMEM);
        cudaFuncSetAttribute(gemm_merge, cudaFuncAttributeMaxDynamicSharedMemorySize, GEMM_DSMEM);
        attr_set = true;
    }

    // 1) mask detect + fp16 conversions
    detect_mask_kernel<<<1, 256>>>(qmask);
    dim3 cgrid((NL * E / 8 + 255) / 256, 3);
    cvt_inputs_kernel<<<cgrid, 256>>>(q, k, v, g_qh_p, g_kh_p, g_vh_p);
    dim3 wgrid((E * E / 8 + 255) / 256, 4);
    cvt_weights_kernel<<<wgrid, 256>>>(Wq, Wk, Wv, Wm);

    // 2) batched QKV projections (fp16 in/out, mask fused in epilogue)
    dim3 ggrid(E / BN, NL / BM, 3);
    gemm_qkv<<<ggrid, 256, GEMM_DSMEM>>>(g_qh_p, g_kh_p, g_vh_p, g_Wh_p,
                                         bq, bk, bv,
                                         g_Qf_p, g_Kf_p, g_Vm_p,
                                         qmask, kmask);

    // 3) KV aggregation (s-split) + reduction
    dim3 kvgrid(NB * H, KV_SPLIT);
    kv_agg_kernel<<<kvgrid, 256>>>(g_Kf_p, g_Vm_p);
    kv_reduce_kernel<<<(NB * H * D * D + NB * H * D + 255) / 256, 256>>>();

    // 4) attention apply (fp16 in/out)
    attn_kernel<<<NB * H * (L / 8), 256>>>(g_Qf_p, g_Oh_p);

    // 5) merge projection (fp16 in, fp32 out)
    dim3 mgrid(E / BN, NL / BM);
    gemm_merge<<<mgrid, 256, GEMM_DSMEM>>>(g_Oh_p, g_Wh_p + 3 * (size_t)E * E, out);
}

// round 17
// speedup vs baseline: 1.2995x; 1.1779x over previous
#include <cuda_runtime.h>
#include <cuda_fp16.h>
#include <math.h>
#include <stdint.h>

// Problem constants
constexpr int NB = 8;
constexpr int L  = 4096;
constexpr int S  = 4096;
constexpr int E  = 256;
constexpr int H  = 8;
constexpr int D  = 32;
constexpr int NL = NB * L;   // 32768
constexpr int NS = NB * S;   // 32768
constexpr float EPS = 1e-6f;
constexpr int KV_SPLIT = 16;

// ---------------- scratch (device globals; no allocation allowed) ----------------
__device__ __half g_Qf[(size_t)NL * E];
__device__ __half g_Kf[(size_t)NS * E];
__device__ __half g_Vm[(size_t)NS * E];
__device__ __half g_Oh[(size_t)NL * E];
__device__ __half g_qh[(size_t)NL * E];
__device__ __half g_kh[(size_t)NS * E];
__device__ __half g_vh[(size_t)NS * E];
__device__ __half g_Wh[4][(size_t)E * E];
__device__ float  g_KV[(size_t)NB * H * D * D];
__device__ float  g_Ksum[(size_t)NB * H * D];
__device__ float  g_KVp[KV_SPLIT][(size_t)NB * H * D * D];
__device__ float  g_Ksump[KV_SPLIT][(size_t)NB * H * D];
__device__ int    g_mask_mode;

// ---------------- helpers ----------------
__device__ __forceinline__ uint32_t smem_u32(const void* p) {
    uint32_t r;
    asm("{ .reg .u64 t; cvta.to.shared.u64 t, %1; cvt.u32.u64 %0, t; }" : "=r"(r) : "l"(p));
    return r;
}

__device__ __forceinline__ uint32_t pack_h2(float x, float y) {
    __half2 h = __floats2half2_rn(x, y);
    return *(uint32_t*)&h;
}

__device__ __forceinline__ void ldmx4(uint32_t (&r)[4], uint32_t addr) {
    asm volatile("ldmatrix.sync.aligned.m8n8.x4.shared.b16 {%0,%1,%2,%3}, [%4];"
                 : "=r"(r[0]), "=r"(r[1]), "=r"(r[2]), "=r"(r[3]) : "r"(addr));
}

__device__ __forceinline__ void mma_f16(float (&d)[4], const uint32_t (&a)[4],
                                        uint32_t b0, uint32_t b1) {
    asm volatile(
        "mma.sync.aligned.m16n8k16.row.col.f32.f16.f16.f32 "
        "{%0,%1,%2,%3}, {%4,%5,%6,%7}, {%8,%9}, {%0,%1,%2,%3};"
        : "+f"(d[0]), "+f"(d[1]), "+f"(d[2]), "+f"(d[3])
        : "r"(a[0]), "r"(a[1]), "r"(a[2]), "r"(a[3]), "r"(b0), "r"(b1));
}

__device__ __forceinline__ void cp_async16(uint32_t dst, const void* src) {
    asm volatile("cp.async.cg.shared.global [%0], [%1], 16;" :: "r"(dst), "l"(src) : "memory");
}
__device__ __forceinline__ void cp_commit() {
    asm volatile("cp.async.commit_group;" ::: "memory");
}
__device__ __forceinline__ void cp_wait1() {
    asm volatile("cp.async.wait_group 1;" ::: "memory");
}

// raw mask element -> 0/1 float (mode from g_mask_mode)
__device__ __forceinline__ float mask_val(const void* m, int i, int mode) {
    if (mode == 0) return ((const unsigned char*)m)[i] ? 1.f : 0.f;
    if (mode == 1) return ((const int*)m)[i] ? 1.f : 0.f;
    return (((const float*)m)[i] != 0.f) ? 1.f : 0.f;
}

// ---------------- combined prep: input cvt + weight cvt + mask detect ----------------
// blocks [0, 12288): inputs (4096 per tensor)   [12288, 12416): weights (32 per matrix)
// block 12416: mask detect
constexpr int PREP_IN_BLKS  = 3 * (NL * E / 8 / 256);   // 12288
constexpr int PREP_W_BLKS   = 4 * (E * E / 8 / 256);    // 128
constexpr int PREP_TOTAL    = PREP_IN_BLKS + PREP_W_BLKS + 1;

__global__ void prep_kernel(const float* __restrict__ q, const float* __restrict__ k,
                            const float* __restrict__ v,
                            const float* __restrict__ w0, const float* __restrict__ w1,
                            const float* __restrict__ w2, const float* __restrict__ w3,
                            __half* __restrict__ dq, __half* __restrict__ dk,
                            __half* __restrict__ dv,
                            const void* __restrict__ qmask)
{
    const int b   = blockIdx.x;
    const int tid = threadIdx.x;
    if (b < PREP_IN_BLKS) {
        const int seg = b / 4096, off = b % 4096;
        const float* s = (seg == 0) ? q : (seg == 1) ? k : v;
        __half*      d = (seg == 0) ? dq : (seg == 1) ? dk : dv;
        size_t i = ((size_t)off * 256 + tid) * 8;
        float4 f0 = *(const float4*)&s[i];
        float4 f1 = *(const float4*)&s[i + 4];
        *(uint4*)&d[i] = make_uint4(pack_h2(f0.x, f0.y), pack_h2(f0.z, f0.w),
                                    pack_h2(f1.x, f1.y), pack_h2(f1.z, f1.w));
    } else if (b < PREP_IN_BLKS + PREP_W_BLKS) {
        const int wb = b - PREP_IN_BLKS;
        const int seg = wb / 32, off = wb % 32;
        const float* s = (seg == 0) ? w0 : (seg == 1) ? w1 : (seg == 2) ? w2 : w3;
        __half*      d = g_Wh[seg];
        size_t i = ((size_t)off * 256 + tid) * 8;
        float4 f0 = *(const float4*)&s[i];
        float4 f1 = *(const float4*)&s[i + 4];
        *(uint4*)&d[i] = make_uint4(pack_h2(f0.x, f0.y), pack_h2(f0.z, f0.w),
                                    pack_h2(f1.x, f1.y), pack_h2(f1.z, f1.w));
    } else {
        __shared__ int s_off1, s_3f;
        if (tid == 0) { s_off1 = 0; s_3f = 0; }
        __syncthreads();
        unsigned char c = ((const unsigned char*)qmask)[tid];
        if ((tid & 3) == 1 && c == 1) atomicOr(&s_off1, 1);
        if (c == 0x3F)                atomicOr(&s_3f, 1);
        __syncthreads();
        if (tid == 0) g_mask_mode = s_off1 ? 0 : (s_3f ? 2 : 1);
    }
}

// ---------------- fp16 tensor-core GEMM core (BK=64, 3-stage cp.async) ----------------
// C = A @ W^T (+bias); mode 0: plain   1: (elu+1)*mask   2: x*mask*scale
// outhalf: 0 -> float* C, 1 -> __half* C.  mask is RAW (converted inline).
#define BM 128
#define BN 128
#define BK 64
#define BUFB 16384
#define NSTAGE 3
constexpr int GEMM_DSMEM = 2 * NSTAGE * BUFB;   // 96KB

__device__ __forceinline__ void gemm_core(
    const __half* __restrict__ A, const __half* __restrict__ W,
    const float* __restrict__ bias, void* __restrict__ Cv,
    const void* __restrict__ mask, float scale, int mode, int outhalf,
    int m0, int n0, unsigned char* dynsm)
{
    const uint32_t sA = smem_u32(dynsm);
    const uint32_t sB = sA + NSTAGE * BUFB;

    const int tid  = threadIdx.x;
    const int wid  = tid >> 5;
    const int lane = tid & 31;
    const int wm   = (wid & 1) * 64;
    const int wn   = (wid >> 1) * 32;
    const int g    = lane >> 2;
    const int tg   = lane & 3;

    int fr[4], fc[4];
    uint32_t foff[4];
#pragma unroll
    for (int p = 0; p < 4; p++) {
        int idx = p * 256 + tid;
        fr[p] = idx >> 3;
        fc[p] = idx & 7;
        foff[p] = (uint32_t)(fr[p] * 128 + ((fc[p] ^ (fr[p] & 7)) << 4));
    }

    const int hA = lane >> 4;
    const int hB = (lane >> 3) & 1;
    uint32_t rbA[4]; int rxA[4];
#pragma unroll
    for (int i = 0; i < 4; i++) {
        int r = wm + i * 16 + (lane & 15);
        rbA[i] = sA + (uint32_t)(r * 128);
        rxA[i] = r & 7;
    }
    uint32_t rbB[2]; int rxB[2];
#pragma unroll
    for (int jp = 0; jp < 2; jp++) {
        int r = wn + (2 * jp + ((lane >> 3) >> 1)) * 8 + (lane & 7);
        rbB[jp] = sB + (uint32_t)(r * 128);
        rxB[jp] = r & 7;
    }

    float acc[4][4][4];
#pragma unroll
    for (int i = 0; i < 4; i++)
#pragma unroll
        for (int j = 0; j < 4; j++)
#pragma unroll
            for (int r = 0; r < 4; r++) acc[i][j][r] = 0.f;

    auto issue_stage = [&](int s) {
        const uint32_t so = (uint32_t)(s % NSTAGE) * BUFB;
#pragma unroll
        for (int p = 0; p < 4; p++) {
            const __half* srcA = A + (size_t)(m0 + fr[p]) * E + s * BK + fc[p] * 8;
            cp_async16(sA + so + foff[p], srcA);
            const __half* srcB = W + (size_t)(n0 + fr[p]) * E + s * BK + fc[p] * 8;
            cp_async16(sB + so + foff[p], srcB);
        }
    };

    issue_stage(0); cp_commit();
    issue_stage(1); cp_commit();

    constexpr int NITER = E / BK;   // 4
#pragma unroll
    for (int c = 0; c < NITER; c++) {
        cp_wait1();
        __syncthreads();
        if (c + 2 < NITER) issue_stage(c + 2);
        cp_commit();

        const uint32_t boff = (uint32_t)(c % NSTAGE) * BUFB;
#pragma unroll
        for (int s = 0; s < 4; s++) {
            uint32_t a[4][4];
#pragma unroll
            for (int i = 0; i < 4; i++) {
                int kc = 2 * s + hA;
                ldmx4(a[i], rbA[i] + boff + (uint32_t)((kc ^ rxA[i]) << 4));
            }
            uint32_t bb[2][4];
#pragma unroll
            for (int jp = 0; jp < 2; jp++) {
                int kc = 2 * s + hB;
                ldmx4(bb[jp], rbB[jp] + boff + (uint32_t)((kc ^ rxB[jp]) << 4));
            }
#pragma unroll
            for (int i = 0; i < 4; i++) {
#pragma unroll
                for (int j = 0; j < 4; j++) {
                    const int jp = j >> 1, hi = j & 1;
                    mma_f16(acc[i][j], a[i], bb[jp][hi * 2], bb[jp][hi * 2 + 1]);
                }
            }
        }
    }

    // epilogue
    const int mmode = (mode != 0) ? g_mask_mode : 0;
    float*  Cf = (float*)Cv;
    __half* Ch = (__half*)Cv;
#pragma unroll
    for (int i = 0; i < 4; i++) {
        const int r0 = m0 + wm + i * 16 + g;
        const int r1 = r0 + 8;
        float rm0 = 0.f, rm1 = 0.f;
        if (mode != 0) { rm0 = mask_val(mask, r0, mmode); rm1 = mask_val(mask, r1, mmode); }
#pragma unroll
        for (int j = 0; j < 4; j++) {
            const int col = n0 + wn + j * 8 + 2 * tg;
            float b0 = 0.f, b1 = 0.f;
            if (bias) { b0 = bias[col]; b1 = bias[col + 1]; }
            float v0 = acc[i][j][0] + b0;
            float v1 = acc[i][j][1] + b1;
            float v2 = acc[i][j][2] + b0;
            float v3 = acc[i][j][3] + b1;
            if (mode == 1) {
                v0 = ((v0 > 0.f) ? (v0 + 1.f) : expf(v0)) * rm0;
                v1 = ((v1 > 0.f) ? (v1 + 1.f) : expf(v1)) * rm0;
                v2 = ((v2 > 0.f) ? (v2 + 1.f) : expf(v2)) * rm1;
                v3 = ((v3 > 0.f) ? (v3 + 1.f) : expf(v3)) * rm1;
            } else if (mode == 2) {
                v0 *= rm0 * scale; v1 *= rm0 * scale;
                v2 *= rm1 * scale; v3 *= rm1 * scale;
            }
            if (outhalf) {
                *(uint32_t*)&Ch[(size_t)r0 * E + col] = pack_h2(v0, v1);
                *(uint32_t*)&Ch[(size_t)r1 * E + col] = pack_h2(v2, v3);
            } else {
                *(float2*)&Cf[(size_t)r0 * E + col] = make_float2(v0, v1);
                *(float2*)&Cf[(size_t)r1 * E + col] = make_float2(v2, v3);
            }
        }
    }
}

// batched QKV projection: blockIdx.z selects {q,k,v}
__global__ __launch_bounds__(256, 2)
void gemm_qkv(const __half* __restrict__ Aq, const __half* __restrict__ Ak,
              const __half* __restrict__ Av, const __half* __restrict__ Wbase,
              const float* __restrict__ bq, const float* __restrict__ bk,
              const float* __restrict__ bv,
              __half* __restrict__ Cq, __half* __restrict__ Ck, __half* __restrict__ Cv_,
              const void* __restrict__ qmask, const void* __restrict__ kmask)
{
    extern __shared__ __align__(16) unsigned char dynsm[];
    const int z = blockIdx.z;
    const __half* A    = (z == 0) ? Aq : (z == 1) ? Ak : Av;
    const __half* W    = Wbase + (size_t)z * E * E;
    const float*  bias = (z == 0) ? bq : (z == 1) ? bk : bv;
    __half*       C    = (z == 0) ? Cq : (z == 1) ? Ck : Cv_;
    const void*   mask = (z == 0) ? qmask : kmask;
    const float   scale = (z == 2) ? (1.0f / (float)S) : 1.0f;
    const int     mode  = (z == 2) ? 2 : 1;
    gemm_core(A, W, bias, C, mask, scale, mode, 1,
              blockIdx.y * BM, blockIdx.x * BN, dynsm);
}

// merge projection: fp16 in, fp32 out, no bias/mask
__global__ __launch_bounds__(256, 2)
void gemm_merge(const __half* __restrict__ A, const __half* __restrict__ W,
                float* __restrict__ C)
{
    extern __shared__ __align__(16) unsigned char dynsm[];
    gemm_core(A, W, nullptr, C, nullptr, 1.0f, 0, 0,
              blockIdx.y * BM, blockIdx.x * BN, dynsm);
}

// ---------------- KV aggregation (s-split, fp16 in) ----------------
__global__ __launch_bounds__(256)
void kv_agg_kernel(const __half* __restrict__ Kf, const __half* __restrict__ Vm)
{
    const int n = blockIdx.x >> 3;
    const int h = blockIdx.x & 7;
    const int split = blockIdx.y;
    const int sbeg = split * (S / KV_SPLIT);
    const int send = sbeg + (S / KV_SPLIT);

    __shared__ float sK[64][40];
    __shared__ float sV[64][40];
    __shared__ float red[4][64][16];

    const int tid = threadIdx.x;
    const int g = tid >> 6;
    const int t = tid & 63;
    const int db = (t >> 3) << 2;
    const int vb = (t & 7) << 2;

    const int lr = tid >> 3;            // 0..31
    const int lc = (tid & 7) << 2;      // 0,4,...,28

    float acc[4][4];
#pragma unroll
    for (int i = 0; i < 4; i++)
#pragma unroll
        for (int j = 0; j < 4; j++) acc[i][j] = 0.f;
    float ksum = 0.f;

    const size_t base = (size_t)n * S * E + (size_t)h * D;

    for (int s0 = sbeg; s0 < send; s0 += 64) {
#pragma unroll
        for (int p = 0; p < 2; p++) {
            int r = lr + p * 32;
            size_t off = base + (size_t)(s0 + r) * E + lc;
            uint2 kr = *(const uint2*)&Kf[off];
            uint2 vr = *(const uint2*)&Vm[off];
            float2 k0 = __half22float2(*(const __half2*)&kr.x);
            float2 k1 = __half22float2(*(const __half2*)&kr.y);
            float2 v0 = __half22float2(*(const __half2*)&vr.x);
            float2 v1 = __half22float2(*(const __half2*)&vr.y);
            *(float4*)&sK[r][lc] = make_float4(k0.x, k0.y, k1.x, k1.y);
            *(float4*)&sV[r][lc] = make_float4(v0.x, v0.y, v1.x, v1.y);
        }
        __syncthreads();

        for (int ss = g; ss < 64; ss += 4) {
            float4 k4 = *(const float4*)&sK[ss][db];
            float4 v4 = *(const float4*)&sV[ss][vb];
            acc[0][0] += k4.x * v4.x; acc[0][1] += k4.x * v4.y; acc[0][2] += k4.x * v4.z; acc[0][3] += k4.x * v4.w;
            acc[1][0] += k4.y * v4.x; acc[1][1] += k4.y * v4.y; acc[1][2] += k4.y * v4.z; acc[1][3] += k4.y * v4.w;
            acc[2][0] += k4.z * v4.x; acc[2][1] += k4.z * v4.y; acc[2][2] += k4.z * v4.z; acc[2][3] += k4.z * v4.w;
            acc[3][0] += k4.w * v4.x; acc[3][1] += k4.w * v4.y; acc[3][2] += k4.w * v4.z; acc[3][3] += k4.w * v4.w;
        }
        if (g == 0 && t < 32) {
#pragma unroll
            for (int ss = 0; ss < 64; ss++) ksum += sK[ss][t];
        }
        __syncthreads();
    }

#pragma unroll
    for (int jd = 0; jd < 4; jd++)
#pragma unroll
        for (int jv = 0; jv < 4; jv++) red[g][t][jd * 4 + jv] = acc[jd][jv];
    __syncthreads();

    const size_t kvbase = (size_t)((n * H + h) * D) * D;
#pragma unroll
    for (int q = 0; q < 4; q++) {
        int o = tid * 4 + q;
        int d = o >> 5, v = o & 31;
        int tt = ((d >> 2) << 3) | (v >> 2);
        int jj = ((d & 3) << 2) | (v & 3);
        float val = red[0][tt][jj] + red[1][tt][jj] + red[2][tt][jj] + red[3][tt][jj];
        g_KVp[split][kvbase + (size_t)d * D + v] = val;
    }
    if (g == 0 && t < 32) g_Ksump[split][(size_t)(n * H + h) * D + t] = ksum;
}

// ---------------- KV partial reduction ----------------
__global__ void kv_reduce_kernel() {
    const int NKV = NB * H * D * D;
    const int NKS = NB * H * D;
    int i = blockIdx.x * blockDim.x + threadIdx.x;
    if (i < NKV) {
        float s = 0.f;
#pragma unroll
        for (int p = 0; p < KV_SPLIT; p++) s += g_KVp[p][i];
        g_KV[i] = s;
    } else if (i < NKV + NKS) {
        int j = i - NKV;
        float s = 0.f;
#pragma unroll
        for (int p = 0; p < KV_SPLIT; p++) s += g_Ksump[p][j];
        g_Ksum[j] = s;
    }
}

// ---------------- attention apply: Oh = fp16( (Qf @ KV) * Z * S ) ----------------
// 4096 blocks; each block = one (n,h) x 64 l-rows (8 warps x 8 rows).
__global__ __launch_bounds__(256)
void attn_kernel(const __half* __restrict__ Qf, __half* __restrict__ O)
{
    const int bid  = blockIdx.x;
    const int n    = bid >> 9;           // H * 64 lgroups = 512 per n
    const int h    = (bid >> 6) & 7;
    const int lgrp = bid & 63;           // 64 rows per block

    __shared__ float sKV[32][32];
    __shared__ float sKs[32];

    const int tid = threadIdx.x;
    const float* kvp = g_KV + (size_t)((n * H + h) * D) * D;
    ((float4*)sKV)[tid] = ((const float4*)kvp)[tid];
    if (tid < 32) sKs[tid] = g_Ksum[(size_t)(n * H + h) * D + tid];
    __syncthreads();

    const int w = tid >> 5, lane = tid & 31;
#pragma unroll
    for (int r = 0; r < 8; r++) {
        const int l = (lgrp << 6) | (w << 3) | r;
        const size_t ro = ((size_t)n * L + l) * E + (size_t)h * D;

        float qf = __half2float(Qf[ro + lane]);
        float z = qf * sKs[lane];
#pragma unroll
        for (int o = 16; o; o >>= 1) z += __shfl_xor_sync(0xffffffffu, z, o);
        float zinv = (float)S / (z + EPS);

        float a0 = 0.f, a1 = 0.f, a2 = 0.f, a3 = 0.f;
#pragma unroll
        for (int d = 0; d < 32; d += 4) {
            a0 += __shfl_sync(0xffffffffu, qf, d)     * sKV[d][lane];
            a1 += __shfl_sync(0xffffffffu, qf, d + 1) * sKV[d + 1][lane];
            a2 += __shfl_sync(0xffffffffu, qf, d + 2) * sKV[d + 2][lane];
            a3 += __shfl_sync(0xffffffffu, qf, d + 3) * sKV[d + 3][lane];
        }
        O[ro + lane] = __float2half(((a0 + a1) + (a2 + a3)) * zinv);
    }
}

// ---------------- launch ----------------
extern "C" void kernel_launch(void* const* d_in, const int* in_sizes, int n_in,
                              void* d_out, int out_size)
{
    const float* q   = (const float*)d_in[0];
    const float* k   = (const float*)d_in[1];
    const float* v   = (const float*)d_in[2];
    const void*  qmask = d_in[3];
    const void*  kmask = d_in[4];
    const float* Wq  = (const float*)d_in[5];
    const float* bq  = (const float*)d_in[6];
    const float* Wk  = (const float*)d_in[7];
    const float* bk  = (const float*)d_in[8];
    const float* Wv  = (const float*)d_in[9];
    const float* bv  = (const float*)d_in[10];
    const float* Wm  = (const float*)d_in[11];
    float* out = (float*)d_out;

    __half* g_Qf_p; cudaGetSymbolAddress((void**)&g_Qf_p, g_Qf);
    __half* g_Kf_p; cudaGetSymbolAddress((void**)&g_Kf_p, g_Kf);
    __half* g_Vm_p; cudaGetSymbolAddress((void**)&g_Vm_p, g_Vm);
    __half* g_Oh_p; cudaGetSymbolAddress((void**)&g_Oh_p, g_Oh);
    __half* g_qh_p; cudaGetSymbolAddress((void**)&g_qh_p, g_qh);
    __half* g_kh_p; cudaGetSymbolAddress((void**)&g_kh_p, g_kh);
    __half* g_vh_p; cudaGetSymbolAddress((void**)&g_vh_p, g_vh);
    __half* g_Wh_p; cudaGetSymbolAddress((void**)&g_Wh_p, g_Wh);

    static bool attr_set = false;
    if (!attr_set) {
        cudaFuncSetAttribute(gemm_qkv,   cudaFuncAttributeMaxDynamicSharedMemorySize, GEMM_DSMEM);
        cudaFuncSetAttribute(gemm_merge, cudaFuncAttributeMaxDynamicSharedMemorySize, GEMM_DSMEM);
        attr_set = true;
    }

    // 1) combined prep (fp16 conversions + mask detect) — one launch
    prep_kernel<<<PREP_TOTAL, 256>>>(q, k, v, Wq, Wk, Wv, Wm,
                                     g_qh_p, g_kh_p, g_vh_p, qmask);

    // 2) batched QKV projections (fp16 in/out, mask fused in epilogue)
    dim3 ggrid(E / BN, NL / BM, 3);
    gemm_qkv<<<ggrid, 256, GEMM_DSMEM>>>(g_qh_p, g_kh_p, g_vh_p, g_Wh_p,
                                         bq, bk, bv,
                                         g_Qf_p, g_Kf_p, g_Vm_p,
                                         qmask, kmask);

    // 3) KV aggregation (s-split x16) + reduction
    dim3 kvgrid(NB * H, KV_SPLIT);
    kv_agg_kernel<<<kvgrid, 256>>>(g_Kf_p, g_Vm_p);
    kv_reduce_kernel<<<(NB * H * D * D + NB * H * D + 255) / 256, 256>>>();

    // 4) attention apply (fp16 in/out; 8 rows per warp)
    attn_kernel<<<NB * H * (L / 64), 256>>>(g_Qf_p, g_Oh_p);

    // 5) merge projection (fp16 in, fp32 out)
    dim3 mgrid(E / BN, NL / BM);
    gemm_merge<<<mgrid, 256, GEMM_DSMEM>>>(g_Oh_p, g_Wh_p + 3 * (size_t)E * E, out);
}